// round 2
// baseline (speedup 1.0000x reference)
#include <cuda_runtime.h>
#include <cuda_bf16.h>
#include <math.h>

#define Bq 64
#define Tq 188
#define Vq 32000
#define BETA 2.0f
#define NSLOT 64

__device__ double        g_acc[NSLOT];   // zero-initialized at load; reset by last block each call
__device__ unsigned int  g_count;        // ditto

__global__ __launch_bounds__(256) void loss_kernel(
    const float* __restrict__ scores,   // [B, T, V]
    const int*   __restrict__ targets,  // [B, T]
    const int*   __restrict__ lengths,  // [B]
    float*       __restrict__ out)
{
    const int bt = blockIdx.x;
    const int b = bt / Tq;
    const int t = bt - b * Tq;
    const bool active = (t < lengths[b]);

    if (active) {
        const float* __restrict__ row = scores + (size_t)bt * Vq;
        const float4* __restrict__ row4 = (const float4*)row;

        // per-thread argmax, first-index tie-break (indices visited in increasing order)
        float vmax = -1e30f;
        int   imax = Vq;
        // Vq/4 = 8000 float4 elems; 256 threads -> 31.25 iters. Unroll x4 for MLP.
        #pragma unroll 4
        for (int i = threadIdx.x; i < Vq / 4; i += blockDim.x) {
            float4 v = row4[i];
            int base = i * 4;
            if (v.x > vmax) { vmax = v.x; imax = base;     }
            if (v.y > vmax) { vmax = v.y; imax = base + 1; }
            if (v.z > vmax) { vmax = v.z; imax = base + 2; }
            if (v.w > vmax) { vmax = v.w; imax = base + 3; }
        }

        // warp reduce: max value, ties -> smaller index
        #pragma unroll
        for (int off = 16; off; off >>= 1) {
            float ov = __shfl_down_sync(0xFFFFFFFFu, vmax, off);
            int   oi = __shfl_down_sync(0xFFFFFFFFu, imax, off);
            if (ov > vmax || (ov == vmax && oi < imax)) { vmax = ov; imax = oi; }
        }

        __shared__ float sv[8];
        __shared__ int   si[8];
        const int wid = threadIdx.x >> 5;
        const int lid = threadIdx.x & 31;
        if (lid == 0) { sv[wid] = vmax; si[wid] = imax; }
        __syncthreads();

        if (threadIdx.x == 0) {
            float fv = sv[0]; int fi = si[0];
            #pragma unroll
            for (int w = 1; w < 8; w++) {
                float ov = sv[w]; int oi = si[w];
                if (ov > fv || (ov == fv && oi < fi)) { fv = ov; fi = oi; }
            }
            const int target = targets[bt];
            const float gathered = __ldg(row + target);  // L2-hot, row just streamed
            const float w = (fi == target && target != 0) ? BETA : 1.0f;
            atomicAdd(&g_acc[bt & (NSLOT - 1)], (double)(-w * logf(gathered)));
        }
    }

    // completion ticket: every block (active or not) arrives; last one finalizes
    // and resets device state so the next graph replay starts clean.
    if (threadIdx.x == 0) {
        __threadfence();                         // make g_acc update visible before count
        unsigned prev = atomicAdd(&g_count, 1u);
        if (prev == gridDim.x - 1) {
            __threadfence();                     // acquire: see all g_acc updates
            double s = 0.0;
            #pragma unroll
            for (int i = 0; i < NSLOT; i++) { s += g_acc[i]; g_acc[i] = 0.0; }
            out[0] = (float)(s / (double)Bq);
            g_count = 0u;
            __threadfence();
        }
    }
}

extern "C" void kernel_launch(void* const* d_in, const int* in_sizes, int n_in,
                              void* d_out, int out_size) {
    const float* scores  = (const float*)d_in[0];
    const int*   targets = (const int*)  d_in[1];
    const int*   lengths = (const int*)  d_in[2];
    float*       out     = (float*)d_out;

    loss_kernel<<<Bq * Tq, 256>>>(scores, targets, lengths, out);
}